// round 15
// baseline (speedup 1.0000x reference)
#include <cuda_runtime.h>
#include <cuda_bf16.h>
#include <math.h>

#define N_NODES 100000
#define N_EDGES 1600000
#define D 64
#define NSTRIPS 6250            // 100000 / 16
#define FULLM 0xffffffffu

// ---------------- scratch (static device globals; no allocations) ----------
__device__ float  g_a1[N_NODES];
__device__ float  g_a2[N_NODES];
__device__ int    g_cnt[N_NODES];       // starts zeroed; re-zeroed by k5 each pass
__device__ int    g_off[N_NODES];
__device__ int    g_cur[N_NODES];
__device__ float4 g_csr[N_EDGES];       // (src_as_int, rf, score, pad)
__device__ float  g_agg[N_NODES * 128]; // cols 0..63: s1-weighted, 64..127: s2-weighted

__device__ __forceinline__ float gelu_exact(float v) {
    return 0.5f * v * (1.0f + erff(v * 0.70710678118654752440f));
}

// split (x,y) into packed bf16x2 hi and lo (residual) pairs
__device__ __forceinline__ void split2(float x, float y, unsigned &hi, unsigned &lo) {
    __nv_bfloat16 hx = __float2bfloat16_rn(x);
    __nv_bfloat16 hy = __float2bfloat16_rn(y);
    float rx = x - __bfloat162float(hx);
    float ry = y - __bfloat162float(hy);
    __nv_bfloat162 h; h.x = hx; h.y = hy;
    __nv_bfloat162 l; l.x = __float2bfloat16_rn(rx); l.y = __float2bfloat16_rn(ry);
    hi = *reinterpret_cast<unsigned*>(&h);
    lo = *reinterpret_cast<unsigned*>(&l);
}

__device__ __forceinline__ void mma_bf16(float c[4],
                                         unsigned a0, unsigned a1, unsigned a2, unsigned a3,
                                         unsigned b0, unsigned b1) {
    asm("mma.sync.aligned.m16n8k16.row.col.f32.bf16.bf16.f32 "
        "{%0,%1,%2,%3},{%4,%5,%6,%7},{%8,%9},{%0,%1,%2,%3};"
        : "+f"(c[0]), "+f"(c[1]), "+f"(c[2]), "+f"(c[3])
        : "r"(a0), "r"(a1), "r"(a2), "r"(a3), "r"(b0), "r"(b1));
}

// 3-term bf16 split accumulate: c += A*B, error ~|al||bl| ~ 4e-6 rel
__device__ __forceinline__ void mma3b(float c[4],
                                      unsigned ah0, unsigned ah1, unsigned ah2, unsigned ah3,
                                      unsigned al0, unsigned al1, unsigned al2, unsigned al3,
                                      unsigned b0h, unsigned b1h, unsigned b0l, unsigned b1l) {
    mma_bf16(c, ah0, ah1, ah2, ah3, b0h, b1h);
    mma_bf16(c, ah0, ah1, ah2, ah3, b0l, b1l);
    mma_bf16(c, al0, al1, al2, al3, b0h, b1h);
}

// ---------------- K12: per-node attention dots + edge histogram (merged) ----
__global__ void k12_prep(const float* __restrict__ x, const float* __restrict__ attw,
                         const int* __restrict__ ei) {
    int gt = blockIdx.x * blockDim.x + threadIdx.x;
    if (gt < N_EDGES) atomicAdd(&g_cnt[ei[N_EDGES + gt]], 1);
    int w = gt >> 5;
    int l = gt & 31;
    if (w >= N_NODES) return;
    const float* xr = x + w * D;
    float v0 = xr[l], v1 = xr[l + 32];
    float s1 = v0 * attw[l]     + v1 * attw[l + 32];
    float s2 = v0 * attw[D + l] + v1 * attw[D + l + 32];
    #pragma unroll
    for (int o = 16; o; o >>= 1) {
        s1 += __shfl_xor_sync(FULLM, s1, o);
        s2 += __shfl_xor_sync(FULLM, s2, o);
    }
    if (l == 0) { g_a1[w] = s1; g_a2[w] = s2; }
}

// ---------------- K3: tiled coalesced single-block scan ---------------------
__global__ void k3_scan() {
    __shared__ int wsum[32];
    int t = threadIdx.x, lane = t & 31, wid = t >> 5;
    int base = 0;
    for (int tile = 0; tile < N_NODES; tile += 1024) {
        int idx = tile + t;
        int v = (idx < N_NODES) ? g_cnt[idx] : 0;
        int inc = v;
        #pragma unroll
        for (int o = 1; o < 32; o <<= 1) {
            int u = __shfl_up_sync(FULLM, inc, o);
            if (lane >= o) inc += u;
        }
        if (lane == 31) wsum[wid] = inc;
        __syncthreads();
        if (wid == 0) {
            int ws = wsum[lane];
            int winc = ws;
            #pragma unroll
            for (int o = 1; o < 32; o <<= 1) {
                int u = __shfl_up_sync(FULLM, winc, o);
                if (lane >= o) winc += u;
            }
            wsum[lane] = winc;
        }
        __syncthreads();
        int excl = base + inc - v + (wid ? wsum[wid - 1] : 0);
        if (idx < N_NODES) { g_off[idx] = excl; g_cur[idx] = excl; }
        base += wsum[31];
        __syncthreads();
    }
}

// ---------------- K4: scatter edges into CSR (packed float4) ----------------
__global__ void k4_scatter(const int* __restrict__ ei, const float* __restrict__ rf) {
    int e = blockIdx.x * blockDim.x + threadIdx.x;
    if (e >= N_EDGES) return;
    int s = ei[e], d = ei[N_EDGES + e];
    int pos = atomicAdd(&g_cur[d], 1);
    g_csr[pos] = make_float4(__int_as_float(s), rf[e], g_a1[s] + g_a2[d], 0.0f);
}

// ---------------- K5: warp-per-node softmax + half-warp float4 gather -------
__global__ void __launch_bounds__(256, 6) k5_agg(
        const float* __restrict__ x, const float* __restrict__ cf) {
    int w = (blockIdx.x * blockDim.x + threadIdx.x) >> 5;
    int l = threadIdx.x & 31;
    if (w >= N_NODES) return;
    int beg = g_off[w], cnt = g_cnt[w];
    float alpha = 1.0f / (1.0f + __expf(-cf[0]));

    float4 ed = make_float4(0.f, 0.f, -1e30f, 0.f);
    if (l < cnt) ed = g_csr[beg + l];

    float m = ed.z;
    for (int i = 32 + l; i < cnt; i += 32) m = fmaxf(m, g_csr[beg + i].z);
    #pragma unroll
    for (int o = 16; o; o >>= 1) m = fmaxf(m, __shfl_xor_sync(FULLM, m, o));

    float e0 = (l < cnt) ? __expf(ed.z - m) : 0.f;
    float den = e0;
    for (int i = 32 + l; i < cnt; i += 32) den += __expf(g_csr[beg + i].z - m);
    #pragma unroll
    for (int o = 16; o; o >>= 1) den += __shfl_xor_sync(FULLM, den, o);
    float inv = (cnt > 0) ? (1.0f / den) : 0.f;

    float w1 = e0 * inv * alpha * ed.y;
    float w2 = e0 * inv * (1.0f - alpha);
    int   sr = __float_as_int(ed.x);

    int h = l >> 4, j = l & 15;
    float4 a1 = make_float4(0.f, 0.f, 0.f, 0.f);
    float4 a2 = make_float4(0.f, 0.f, 0.f, 0.f);

    int n0  = cnt < 32 ? cnt : 32;
    int n0e = (n0 + 1) & ~1;
    int i = 0;
    for (; i + 8 <= n0e; i += 8) {
        #pragma unroll
        for (int b = 0; b < 4; b++) {
            int   e  = i + 2 * b + h;
            int   se = __shfl_sync(FULLM, sr, e);
            float p  = __shfl_sync(FULLM, w1, e);
            float q  = __shfl_sync(FULLM, w2, e);
            float4 v = *reinterpret_cast<const float4*>(x + se * D + 4 * j);
            a1.x += p * v.x; a1.y += p * v.y; a1.z += p * v.z; a1.w += p * v.w;
            a2.x += q * v.x; a2.y += q * v.y; a2.z += q * v.z; a2.w += q * v.w;
        }
    }
    for (; i < n0e; i += 2) {
        int   e  = i + h;
        int   se = __shfl_sync(FULLM, sr, e);
        float p  = __shfl_sync(FULLM, w1, e);
        float q  = __shfl_sync(FULLM, w2, e);
        float4 v = *reinterpret_cast<const float4*>(x + se * D + 4 * j);
        a1.x += p * v.x; a1.y += p * v.y; a1.z += p * v.z; a1.w += p * v.w;
        a2.x += q * v.x; a2.y += q * v.y; a2.z += q * v.z; a2.w += q * v.w;
    }
    for (int base2 = 32; base2 < cnt; base2 += 32) {
        int k = base2 + l;
        float4 e2 = make_float4(0.f, 0.f, 0.f, 0.f);
        float ew = 0.f;
        if (k < cnt) { e2 = g_csr[beg + k]; ew = __expf(e2.z - m) * inv; }
        float u1 = ew * alpha * e2.y;
        float u2 = ew * (1.0f - alpha);
        int  s2r = __float_as_int(e2.x);
        int lim = cnt - base2; if (lim > 32) lim = 32;
        int lime = (lim + 1) & ~1;
        for (int ii = 0; ii < lime; ii += 2) {
            int   e  = ii + h;
            int   se = __shfl_sync(FULLM, s2r, e);
            float p  = __shfl_sync(FULLM, u1, e);
            float q  = __shfl_sync(FULLM, u2, e);
            float4 v = *reinterpret_cast<const float4*>(x + se * D + 4 * j);
            a1.x += p * v.x; a1.y += p * v.y; a1.z += p * v.z; a1.w += p * v.w;
            a2.x += q * v.x; a2.y += q * v.y; a2.z += q * v.z; a2.w += q * v.w;
        }
    }
    a1.x += __shfl_xor_sync(FULLM, a1.x, 16);
    a1.y += __shfl_xor_sync(FULLM, a1.y, 16);
    a1.z += __shfl_xor_sync(FULLM, a1.z, 16);
    a1.w += __shfl_xor_sync(FULLM, a1.w, 16);
    a2.x += __shfl_xor_sync(FULLM, a2.x, 16);
    a2.y += __shfl_xor_sync(FULLM, a2.y, 16);
    a2.z += __shfl_xor_sync(FULLM, a2.z, 16);
    a2.w += __shfl_xor_sync(FULLM, a2.w, 16);
    float4 sel = h ? a2 : a1;
    *reinterpret_cast<float4*>(g_agg + w * 128 + 4 * l) = sel;
    if (l == 0) g_cnt[w] = 0;
}

// ---------------- K67 fused: full post-aggregation pipeline -----------------
// out = LN2( gelu( LN1(gelu(agg@[Wp;Wn]^T)+x) @ W1^T + b1 ) @ W2^T + b2 + h )
// h and t never leave registers. The MMA C-fragment layout (cols nt*8+2*tig,
// rows r0/r1 at gid, gid+8) IS the bf16-pair A-fragment layout of the next
// GEMM, so split2 on the accumulators feeds the next phase directly.
// Separate sH/sL arrays (R10-proven), strides 72 / 136 (stride mod 32 == 8
// -> full-warp scalar LDS conflict-free).
#define SN6 72                    // rows of length 64
#define SN7 136                   // rows of length 128
__global__ void __launch_bounds__(256) k67_fused(
        float* __restrict__ out, const float* __restrict__ x,
        const float* __restrict__ Wp, const float* __restrict__ Wn,
        const float* __restrict__ g1, const float* __restrict__ b1ln,
        const float* __restrict__ W1, const float* __restrict__ B1,
        const float* __restrict__ W2, const float* __restrict__ B2,
        const float* __restrict__ g2, const float* __restrict__ b2ln) {
    __shared__ unsigned sH[64 * SN6];       // 4608 >= 32*SN7 = 4352
    __shared__ unsigned sL[64 * SN6];
    int tid = threadIdx.x;

    // ---- weights phase A: B = [Wp;Wn], pairs [kp<64][n<64] ----
    for (int i = tid; i < 4096; i += 256) {
        int kp = i >> 6, n = i & 63;
        float2 wv = (kp < 32)
            ? *reinterpret_cast<const float2*>(Wp + n * 64 + 2 * kp)
            : *reinterpret_cast<const float2*>(Wn + n * 64 + 2 * (kp - 32));
        unsigned hh, ll;
        split2(wv.x, wv.y, hh, ll);
        sH[kp * SN6 + n] = hh;
        sL[kp * SN6 + n] = ll;
    }
    __syncthreads();

    int wid = tid >> 5, lane = tid & 31;
    int gid = lane >> 2, tig = lane & 3;
    int strip = blockIdx.x * 8 + wid;
    if (strip >= NSTRIPS) strip = NSTRIPS - 1;   // clamp: duplicate identical work
    int r0 = strip * 16 + gid, r1 = r0 + 8;

    // ---- GEMM1: c1 = agg @ [Wp;Wn]^T  (K=128) ----
    float h[8][4];
    #pragma unroll
    for (int nt = 0; nt < 8; nt++)
        h[nt][0] = h[nt][1] = h[nt][2] = h[nt][3] = 0.f;

    #pragma unroll 2
    for (int kk = 0; kk < 8; kk++) {
        int kb = kk * 16, kp0 = kk * 8;
        float2 A0 = *reinterpret_cast<const float2*>(g_agg + r0 * 128 + kb + 2 * tig);
        float2 A1 = *reinterpret_cast<const float2*>(g_agg + r1 * 128 + kb + 2 * tig);
        float2 A2 = *reinterpret_cast<const float2*>(g_agg + r0 * 128 + kb + 2 * tig + 8);
        float2 A3 = *reinterpret_cast<const float2*>(g_agg + r1 * 128 + kb + 2 * tig + 8);
        unsigned ah0, al0, ah1, al1, ah2, al2, ah3, al3;
        split2(A0.x, A0.y, ah0, al0);
        split2(A1.x, A1.y, ah1, al1);
        split2(A2.x, A2.y, ah2, al2);
        split2(A3.x, A3.y, ah3, al3);
        const unsigned* rh0 = &sH[(kp0 + tig) * SN6];
        const unsigned* rh1 = &sH[(kp0 + tig + 4) * SN6];
        const unsigned* rl0 = &sL[(kp0 + tig) * SN6];
        const unsigned* rl1 = &sL[(kp0 + tig + 4) * SN6];
        #pragma unroll
        for (int nt = 0; nt < 8; nt++) {
            int bi = nt * 8 + gid;
            mma3b(h[nt], ah0, ah1, ah2, ah3, al0, al1, al2, al3,
                  rh0[bi], rh1[bi], rl0[bi], rl1[bi]);
        }
    }

    // ---- epilogue 1: h = LN1(gelu(c1) + x) (stays in registers) ----
    {
        float s0 = 0.f, q0 = 0.f, s1 = 0.f, q1 = 0.f;
        #pragma unroll
        for (int nt = 0; nt < 8; nt++) {
            int col = nt * 8 + 2 * tig;
            float2 xv0 = *reinterpret_cast<const float2*>(x + r0 * D + col);
            float2 xv1 = *reinterpret_cast<const float2*>(x + r1 * D + col);
            h[nt][0] = gelu_exact(h[nt][0]) + xv0.x;
            h[nt][1] = gelu_exact(h[nt][1]) + xv0.y;
            h[nt][2] = gelu_exact(h[nt][2]) + xv1.x;
            h[nt][3] = gelu_exact(h[nt][3]) + xv1.y;
            s0 += h[nt][0] + h[nt][1]; q0 += h[nt][0] * h[nt][0] + h[nt][1] * h[nt][1];
            s1 += h[nt][2] + h[nt][3]; q1 += h[nt][2] * h[nt][2] + h[nt][3] * h[nt][3];
        }
        #pragma unroll
        for (int o = 1; o <= 2; o <<= 1) {
            s0 += __shfl_xor_sync(FULLM, s0, o);
            q0 += __shfl_xor_sync(FULLM, q0, o);
            s1 += __shfl_xor_sync(FULLM, s1, o);
            q1 += __shfl_xor_sync(FULLM, q1, o);
        }
        float mu0 = s0 * (1.0f / 64.0f), var0 = q0 * (1.0f / 64.0f) - mu0 * mu0;
        float mu1 = s1 * (1.0f / 64.0f), var1 = q1 * (1.0f / 64.0f) - mu1 * mu1;
        float rs0 = rsqrtf(var0 + 1e-5f), rs1 = rsqrtf(var1 + 1e-5f);
        #pragma unroll
        for (int nt = 0; nt < 8; nt++) {
            int col = nt * 8 + 2 * tig;
            float2 gg = *reinterpret_cast<const float2*>(g1 + col);
            float2 bb = *reinterpret_cast<const float2*>(b1ln + col);
            h[nt][0] = (h[nt][0] - mu0) * rs0 * gg.x + bb.x;
            h[nt][1] = (h[nt][1] - mu0) * rs0 * gg.y + bb.y;
            h[nt][2] = (h[nt][2] - mu1) * rs1 * gg.x + bb.x;
            h[nt][3] = (h[nt][3] - mu1) * rs1 * gg.y + bb.y;
        }
    }

    // ---- weights phase B: W1 pairs [kp<32][j<128], stride SN7 ----
    __syncthreads();
    for (int i = tid; i < 4096; i += 256) {
        int kp = i >> 7, j = i & 127;
        float2 wv = *reinterpret_cast<const float2*>(W1 + j * 64 + 2 * kp);
        unsigned hh, ll;
        split2(wv.x, wv.y, hh, ll);
        sH[kp * SN7 + j] = hh;
        sL[kp * SN7 + j] = ll;
    }
    __syncthreads();

    // ---- GEMM2: t = gelu(h @ W1^T + b1)  (K=64, A direct from h regs) ----
    float t[16][4];
    #pragma unroll
    for (int nt = 0; nt < 16; nt++)
        t[nt][0] = t[nt][1] = t[nt][2] = t[nt][3] = 0.f;

    #pragma unroll
    for (int kk = 0; kk < 4; kk++) {
        int kp0 = kk * 8;
        unsigned ah0, al0, ah1, al1, ah2, al2, ah3, al3;
        split2(h[2 * kk][0],     h[2 * kk][1],     ah0, al0);
        split2(h[2 * kk][2],     h[2 * kk][3],     ah1, al1);
        split2(h[2 * kk + 1][0], h[2 * kk + 1][1], ah2, al2);
        split2(h[2 * kk + 1][2], h[2 * kk + 1][3], ah3, al3);
        const unsigned* rh0 = &sH[(kp0 + tig) * SN7];
        const unsigned* rh1 = &sH[(kp0 + tig + 4) * SN7];
        const unsigned* rl0 = &sL[(kp0 + tig) * SN7];
        const unsigned* rl1 = &sL[(kp0 + tig + 4) * SN7];
        #pragma unroll
        for (int nt = 0; nt < 16; nt++) {
            int bi = nt * 8 + gid;
            mma3b(t[nt], ah0, ah1, ah2, ah3, al0, al1, al2, al3,
                  rh0[bi], rh1[bi], rl0[bi], rl1[bi]);
        }
    }
    #pragma unroll
    for (int nt = 0; nt < 16; nt++) {
        int col = nt * 8 + 2 * tig;
        float2 bb = *reinterpret_cast<const float2*>(B1 + col);
        t[nt][0] = gelu_exact(t[nt][0] + bb.x);
        t[nt][1] = gelu_exact(t[nt][1] + bb.y);
        t[nt][2] = gelu_exact(t[nt][2] + bb.x);
        t[nt][3] = gelu_exact(t[nt][3] + bb.y);
    }

    // ---- weights phase C: W2 pairs [kp<64][n<64], stride SN6 ----
    __syncthreads();
    for (int i = tid; i < 4096; i += 256) {
        int kp = i >> 6, n = i & 63;
        float2 wv = *reinterpret_cast<const float2*>(W2 + n * 128 + 2 * kp);
        unsigned hh, ll;
        split2(wv.x, wv.y, hh, ll);
        sH[kp * SN6 + n] = hh;
        sL[kp * SN6 + n] = ll;
    }
    __syncthreads();

    // ---- GEMM3: c3 = t @ W2^T  (K=128, A direct from t regs) ----
    float c3[8][4];
    #pragma unroll
    for (int nt = 0; nt < 8; nt++)
        c3[nt][0] = c3[nt][1] = c3[nt][2] = c3[nt][3] = 0.f;

    #pragma unroll
    for (int kk = 0; kk < 8; kk++) {
        int kp0 = kk * 8;
        unsigned ah0, al0, ah1, al1, ah2, al2, ah3, al3;
        split2(t[2 * kk][0],     t[2 * kk][1],     ah0, al0);
        split2(t[2 * kk][2],     t[2 * kk][3],     ah1, al1);
        split2(t[2 * kk + 1][0], t[2 * kk + 1][1], ah2, al2);
        split2(t[2 * kk + 1][2], t[2 * kk + 1][3], ah3, al3);
        const unsigned* rh0 = &sH[(kp0 + tig) * SN6];
        const unsigned* rh1 = &sH[(kp0 + tig + 4) * SN6];
        const unsigned* rl0 = &sL[(kp0 + tig) * SN6];
        const unsigned* rl1 = &sL[(kp0 + tig + 4) * SN6];
        #pragma unroll
        for (int nt = 0; nt < 8; nt++) {
            int bi = nt * 8 + gid;
            mma3b(c3[nt], ah0, ah1, ah2, ah3, al0, al1, al2, al3,
                  rh0[bi], rh1[bi], rl0[bi], rl1[bi]);
        }
    }

    // ---- epilogue 2: out = LN2(c3 + b2 + h) ----
    float s0 = 0.f, q0 = 0.f, s1 = 0.f, q1 = 0.f;
    #pragma unroll
    for (int nt = 0; nt < 8; nt++) {
        int col = nt * 8 + 2 * tig;
        float2 bb = *reinterpret_cast<const float2*>(B2 + col);
        c3[nt][0] += bb.x + h[nt][0];
        c3[nt][1] += bb.y + h[nt][1];
        c3[nt][2] += bb.x + h[nt][2];
        c3[nt][3] += bb.y + h[nt][3];
        s0 += c3[nt][0] + c3[nt][1]; q0 += c3[nt][0] * c3[nt][0] + c3[nt][1] * c3[nt][1];
        s1 += c3[nt][2] + c3[nt][3]; q1 += c3[nt][2] * c3[nt][2] + c3[nt][3] * c3[nt][3];
    }
    #pragma unroll
    for (int o = 1; o <= 2; o <<= 1) {
        s0 += __shfl_xor_sync(FULLM, s0, o);
        q0 += __shfl_xor_sync(FULLM, q0, o);
        s1 += __shfl_xor_sync(FULLM, s1, o);
        q1 += __shfl_xor_sync(FULLM, q1, o);
    }
    float mu0 = s0 * (1.0f / 64.0f), var0 = q0 * (1.0f / 64.0f) - mu0 * mu0;
    float mu1 = s1 * (1.0f / 64.0f), var1 = q1 * (1.0f / 64.0f) - mu1 * mu1;
    float rs0 = rsqrtf(var0 + 1e-5f), rs1 = rsqrtf(var1 + 1e-5f);
    #pragma unroll
    for (int nt = 0; nt < 8; nt++) {
        int col = nt * 8 + 2 * tig;
        float2 gg = *reinterpret_cast<const float2*>(g2 + col);
        float2 bb = *reinterpret_cast<const float2*>(b2ln + col);
        float2 o0 = make_float2((c3[nt][0] - mu0) * rs0 * gg.x + bb.x,
                                (c3[nt][1] - mu0) * rs0 * gg.y + bb.y);
        float2 o1 = make_float2((c3[nt][2] - mu1) * rs1 * gg.x + bb.x,
                                (c3[nt][3] - mu1) * rs1 * gg.y + bb.y);
        *reinterpret_cast<float2*>(out + r0 * D + col) = o0;
        *reinterpret_cast<float2*>(out + r1 * D + col) = o1;
    }
}

// ---------------- launcher --------------------------------------------------
extern "C" void kernel_launch(void* const* d_in, const int* in_sizes, int n_in,
                              void* d_out, int out_size) {
    (void)in_sizes; (void)n_in; (void)out_size;
    const float* x    = (const float*)d_in[0];
    const int*   ei   = (const int*)  d_in[1];
    const float* rf   = (const float*)d_in[2];
    const float* Wp   = (const float*)d_in[3];
    const float* Wn   = (const float*)d_in[4];
    const float* attw = (const float*)d_in[5];
    const float* cf   = (const float*)d_in[6];
    const float* W1   = (const float*)d_in[7];
    const float* B1   = (const float*)d_in[8];
    const float* W2   = (const float*)d_in[9];
    const float* B2   = (const float*)d_in[10];
    const float* g1   = (const float*)d_in[11];
    const float* b1   = (const float*)d_in[12];
    const float* g2   = (const float*)d_in[13];
    const float* b2   = (const float*)d_in[14];
    float* out = (float*)d_out;

    const int GBLK = (NSTRIPS + 7) / 8;      // 782

    k12_prep<<<N_NODES / 8, 256>>>(x, attw, ei);
    k3_scan<<<1, 1024>>>();
    k4_scatter<<<N_EDGES / 256, 256>>>(ei, rf);
    k5_agg<<<N_NODES / 8, 256>>>(x, cf);
    k67_fused<<<GBLK, 256>>>(out, x, Wp, Wn, g1, b1, W1, B1, W2, B2, g2, b2);
}

// round 17
// speedup vs baseline: 1.4164x; 1.4164x over previous
#include <cuda_runtime.h>
#include <cuda_bf16.h>
#include <math.h>

#define N_NODES 100000
#define N_EDGES 1600000
#define D 64
#define NSTRIPS 6250            // 100000 / 16
#define NTILE 98                // ceil(100000 / 1024)
#define FULLM 0xffffffffu

// ---------------- scratch (static device globals; no allocations) ----------
__device__ float  g_a1[N_NODES];
__device__ float  g_a2[N_NODES];
__device__ int    g_cnt[N_NODES];       // starts zeroed; re-zeroed by k5 each pass
__device__ int    g_off[N_NODES];
__device__ int    g_cur[N_NODES];
__device__ int    g_tile[NTILE];
__device__ float4 g_csr[N_EDGES];       // (src_as_int, rf, score, pad)
__device__ float  g_agg[N_NODES * 128]; // cols 0..63: s1-weighted, 64..127: s2-weighted
__device__ float  g_h[N_NODES * D];

__device__ __forceinline__ float gelu_exact(float v) {
    return 0.5f * v * (1.0f + erff(v * 0.70710678118654752440f));
}

// split (x,y) into packed bf16x2 hi and lo (residual) pairs
__device__ __forceinline__ void split2(float x, float y, unsigned &hi, unsigned &lo) {
    __nv_bfloat16 hx = __float2bfloat16_rn(x);
    __nv_bfloat16 hy = __float2bfloat16_rn(y);
    float rx = x - __bfloat162float(hx);
    float ry = y - __bfloat162float(hy);
    __nv_bfloat162 h; h.x = hx; h.y = hy;
    __nv_bfloat162 l; l.x = __float2bfloat16_rn(rx); l.y = __float2bfloat16_rn(ry);
    hi = *reinterpret_cast<unsigned*>(&h);
    lo = *reinterpret_cast<unsigned*>(&l);
}

__device__ __forceinline__ void mma_bf16(float c[4],
                                         unsigned a0, unsigned a1, unsigned a2, unsigned a3,
                                         unsigned b0, unsigned b1) {
    asm("mma.sync.aligned.m16n8k16.row.col.f32.bf16.bf16.f32 "
        "{%0,%1,%2,%3},{%4,%5,%6,%7},{%8,%9},{%0,%1,%2,%3};"
        : "+f"(c[0]), "+f"(c[1]), "+f"(c[2]), "+f"(c[3])
        : "r"(a0), "r"(a1), "r"(a2), "r"(a3), "r"(b0), "r"(b1));
}

// 3-term bf16 split accumulate: c += A*B, error ~|al||bl| ~ 4e-6 rel
__device__ __forceinline__ void mma3b(float c[4],
                                      unsigned ah0, unsigned ah1, unsigned ah2, unsigned ah3,
                                      unsigned al0, unsigned al1, unsigned al2, unsigned al3,
                                      unsigned b0h, unsigned b1h, unsigned b0l, unsigned b1l) {
    mma_bf16(c, ah0, ah1, ah2, ah3, b0h, b1h);
    mma_bf16(c, ah0, ah1, ah2, ah3, b0l, b1l);
    mma_bf16(c, al0, al1, al2, al3, b0h, b1h);
}

// ---------------- K12: per-node attention dots + edge histogram (merged) ----
__global__ void k12_prep(const float* __restrict__ x, const float* __restrict__ attw,
                         const int* __restrict__ ei) {
    int gt = blockIdx.x * blockDim.x + threadIdx.x;
    if (gt < N_EDGES) atomicAdd(&g_cnt[ei[N_EDGES + gt]], 1);
    int w = gt >> 5;
    int l = gt & 31;
    if (w >= N_NODES) return;
    const float* xr = x + w * D;
    float v0 = xr[l], v1 = xr[l + 32];
    float s1 = v0 * attw[l]     + v1 * attw[l + 32];
    float s2 = v0 * attw[D + l] + v1 * attw[D + l + 32];
    #pragma unroll
    for (int o = 16; o; o >>= 1) {
        s1 += __shfl_xor_sync(FULLM, s1, o);
        s2 += __shfl_xor_sync(FULLM, s2, o);
    }
    if (l == 0) { g_a1[w] = s1; g_a2[w] = s2; }
}

// ---------------- K3a: per-tile scans + tile totals (parallel) --------------
__global__ void k3a_scan() {
    __shared__ int wsum[32];
    int b = blockIdx.x, t = threadIdx.x, lane = t & 31, wid = t >> 5;
    int idx = b * 1024 + t;
    int v = (idx < N_NODES) ? g_cnt[idx] : 0;
    int inc = v;
    #pragma unroll
    for (int o = 1; o < 32; o <<= 1) {
        int u = __shfl_up_sync(FULLM, inc, o);
        if (lane >= o) inc += u;
    }
    if (lane == 31) wsum[wid] = inc;
    __syncthreads();
    if (wid == 0) {
        int winc = wsum[lane];
        #pragma unroll
        for (int o = 1; o < 32; o <<= 1) {
            int u = __shfl_up_sync(FULLM, winc, o);
            if (lane >= o) winc += u;
        }
        wsum[lane] = winc;
    }
    __syncthreads();
    int excl = inc - v + (wid ? wsum[wid - 1] : 0);
    if (idx < N_NODES) g_off[idx] = excl;      // within-tile exclusive
    if (t == 0) g_tile[b] = wsum[31];          // tile total
}

// ---------------- K3b: single-warp scan of tile totals ----------------------
__global__ void k3b_scan() {
    int lane = threadIdx.x;
    int carry = 0;
    for (int base = 0; base < NTILE; base += 32) {
        int i = base + lane;
        int v = (i < NTILE) ? g_tile[i] : 0;
        int inc = v;
        #pragma unroll
        for (int o = 1; o < 32; o <<= 1) {
            int u = __shfl_up_sync(FULLM, inc, o);
            if (lane >= o) inc += u;
        }
        if (i < NTILE) g_tile[i] = carry + inc - v;   // exclusive prefix
        carry += __shfl_sync(FULLM, inc, 31);
    }
}

// ---------------- K3c: add tile prefixes ------------------------------------
__global__ void k3c_apply() {
    int b = blockIdx.x;
    int idx = b * 1024 + threadIdx.x;
    if (idx >= N_NODES) return;
    int off = g_off[idx] + g_tile[b];
    g_off[idx] = off;
    g_cur[idx] = off;
}

// ---------------- K4: scatter edges into CSR (packed float4) ----------------
__global__ void k4_scatter(const int* __restrict__ ei, const float* __restrict__ rf) {
    int e = blockIdx.x * blockDim.x + threadIdx.x;
    if (e >= N_EDGES) return;
    int s = ei[e], d = ei[N_EDGES + e];
    int pos = atomicAdd(&g_cur[d], 1);
    g_csr[pos] = make_float4(__int_as_float(s), rf[e], g_a1[s] + g_a2[d], 0.0f);
}

// ---------------- K5: warp-per-node softmax + half-warp float4 gather -------
__global__ void __launch_bounds__(256, 6) k5_agg(
        const float* __restrict__ x, const float* __restrict__ cf) {
    int w = (blockIdx.x * blockDim.x + threadIdx.x) >> 5;
    int l = threadIdx.x & 31;
    if (w >= N_NODES) return;
    int beg = g_off[w], cnt = g_cnt[w];
    float alpha = 1.0f / (1.0f + __expf(-cf[0]));

    float4 ed = make_float4(0.f, 0.f, -1e30f, 0.f);
    if (l < cnt) ed = g_csr[beg + l];

    float m = ed.z;
    for (int i = 32 + l; i < cnt; i += 32) m = fmaxf(m, g_csr[beg + i].z);
    #pragma unroll
    for (int o = 16; o; o >>= 1) m = fmaxf(m, __shfl_xor_sync(FULLM, m, o));

    float e0 = (l < cnt) ? __expf(ed.z - m) : 0.f;
    float den = e0;
    for (int i = 32 + l; i < cnt; i += 32) den += __expf(g_csr[beg + i].z - m);
    #pragma unroll
    for (int o = 16; o; o >>= 1) den += __shfl_xor_sync(FULLM, den, o);
    float inv = (cnt > 0) ? (1.0f / den) : 0.f;

    float w1 = e0 * inv * alpha * ed.y;
    float w2 = e0 * inv * (1.0f - alpha);
    int   sr = __float_as_int(ed.x);

    int h = l >> 4, j = l & 15;
    float4 a1 = make_float4(0.f, 0.f, 0.f, 0.f);
    float4 a2 = make_float4(0.f, 0.f, 0.f, 0.f);

    int n0  = cnt < 32 ? cnt : 32;
    int n0e = (n0 + 1) & ~1;
    int i = 0;
    for (; i + 8 <= n0e; i += 8) {
        #pragma unroll
        for (int b = 0; b < 4; b++) {
            int   e  = i + 2 * b + h;
            int   se = __shfl_sync(FULLM, sr, e);
            float p  = __shfl_sync(FULLM, w1, e);
            float q  = __shfl_sync(FULLM, w2, e);
            float4 v = *reinterpret_cast<const float4*>(x + se * D + 4 * j);
            a1.x += p * v.x; a1.y += p * v.y; a1.z += p * v.z; a1.w += p * v.w;
            a2.x += q * v.x; a2.y += q * v.y; a2.z += q * v.z; a2.w += q * v.w;
        }
    }
    for (; i < n0e; i += 2) {
        int   e  = i + h;
        int   se = __shfl_sync(FULLM, sr, e);
        float p  = __shfl_sync(FULLM, w1, e);
        float q  = __shfl_sync(FULLM, w2, e);
        float4 v = *reinterpret_cast<const float4*>(x + se * D + 4 * j);
        a1.x += p * v.x; a1.y += p * v.y; a1.z += p * v.z; a1.w += p * v.w;
        a2.x += q * v.x; a2.y += q * v.y; a2.z += q * v.z; a2.w += q * v.w;
    }
    for (int base2 = 32; base2 < cnt; base2 += 32) {
        int k = base2 + l;
        float4 e2 = make_float4(0.f, 0.f, 0.f, 0.f);
        float ew = 0.f;
        if (k < cnt) { e2 = g_csr[beg + k]; ew = __expf(e2.z - m) * inv; }
        float u1 = ew * alpha * e2.y;
        float u2 = ew * (1.0f - alpha);
        int  s2r = __float_as_int(e2.x);
        int lim = cnt - base2; if (lim > 32) lim = 32;
        int lime = (lim + 1) & ~1;
        for (int ii = 0; ii < lime; ii += 2) {
            int   e  = ii + h;
            int   se = __shfl_sync(FULLM, s2r, e);
            float p  = __shfl_sync(FULLM, u1, e);
            float q  = __shfl_sync(FULLM, u2, e);
            float4 v = *reinterpret_cast<const float4*>(x + se * D + 4 * j);
            a1.x += p * v.x; a1.y += p * v.y; a1.z += p * v.z; a1.w += p * v.w;
            a2.x += q * v.x; a2.y += q * v.y; a2.z += q * v.z; a2.w += q * v.w;
        }
    }
    a1.x += __shfl_xor_sync(FULLM, a1.x, 16);
    a1.y += __shfl_xor_sync(FULLM, a1.y, 16);
    a1.z += __shfl_xor_sync(FULLM, a1.z, 16);
    a1.w += __shfl_xor_sync(FULLM, a1.w, 16);
    a2.x += __shfl_xor_sync(FULLM, a2.x, 16);
    a2.y += __shfl_xor_sync(FULLM, a2.y, 16);
    a2.z += __shfl_xor_sync(FULLM, a2.z, 16);
    a2.w += __shfl_xor_sync(FULLM, a2.w, 16);
    float4 sel = h ? a2 : a1;
    *reinterpret_cast<float4*>(g_agg + w * 128 + 4 * l) = sel;
    if (l == 0) g_cnt[w] = 0;
}

// ---------------- K6: h = LN1(gelu(agg @ [Wp;Wn]^T) + x)  (bf16x3 MMA) ------
#define SN6 72
__global__ void __launch_bounds__(256) k6_gemm_ln1(
        const float* __restrict__ x,
        const float* __restrict__ Wp, const float* __restrict__ Wn,
        const float* __restrict__ g1, const float* __restrict__ b1) {
    __shared__ unsigned sH[64 * SN6];
    __shared__ unsigned sL[64 * SN6];
    int tid = threadIdx.x;
    for (int i = tid; i < 4096; i += 256) {
        int kp = i >> 6, n = i & 63;
        float2 wv = (kp < 32)
            ? *reinterpret_cast<const float2*>(Wp + n * 64 + 2 * kp)
            : *reinterpret_cast<const float2*>(Wn + n * 64 + 2 * (kp - 32));
        unsigned h, l;
        split2(wv.x, wv.y, h, l);
        sH[kp * SN6 + n] = h;
        sL[kp * SN6 + n] = l;
    }
    __syncthreads();
    int wid = tid >> 5, lane = tid & 31;
    int gid = lane >> 2, tig = lane & 3;
    int strip = blockIdx.x * 8 + wid;
    if (strip >= NSTRIPS) return;
    int r0 = strip * 16 + gid, r1 = r0 + 8;

    float c[8][4];
    #pragma unroll
    for (int nt = 0; nt < 8; nt++)
        c[nt][0] = c[nt][1] = c[nt][2] = c[nt][3] = 0.f;

    #pragma unroll 2
    for (int kk = 0; kk < 8; kk++) {
        int kb = kk * 16, kp0 = kk * 8;
        float2 A0 = *reinterpret_cast<const float2*>(g_agg + r0 * 128 + kb + 2 * tig);
        float2 A1 = *reinterpret_cast<const float2*>(g_agg + r1 * 128 + kb + 2 * tig);
        float2 A2 = *reinterpret_cast<const float2*>(g_agg + r0 * 128 + kb + 2 * tig + 8);
        float2 A3 = *reinterpret_cast<const float2*>(g_agg + r1 * 128 + kb + 2 * tig + 8);
        unsigned ah0, al0, ah1, al1, ah2, al2, ah3, al3;
        split2(A0.x, A0.y, ah0, al0);
        split2(A1.x, A1.y, ah1, al1);
        split2(A2.x, A2.y, ah2, al2);
        split2(A3.x, A3.y, ah3, al3);
        const unsigned* rh0 = &sH[(kp0 + tig) * SN6];
        const unsigned* rh1 = &sH[(kp0 + tig + 4) * SN6];
        const unsigned* rl0 = &sL[(kp0 + tig) * SN6];
        const unsigned* rl1 = &sL[(kp0 + tig + 4) * SN6];
        #pragma unroll
        for (int nt = 0; nt < 8; nt++) {
            int bi = nt * 8 + gid;
            mma3b(c[nt], ah0, ah1, ah2, ah3, al0, al1, al2, al3,
                  rh0[bi], rh1[bi], rl0[bi], rl1[bi]);
        }
    }
    float s0 = 0.f, q0 = 0.f, s1 = 0.f, q1 = 0.f;
    #pragma unroll
    for (int nt = 0; nt < 8; nt++) {
        int col = nt * 8 + 2 * tig;
        float2 xv0 = *reinterpret_cast<const float2*>(x + r0 * D + col);
        float2 xv1 = *reinterpret_cast<const float2*>(x + r1 * D + col);
        c[nt][0] = gelu_exact(c[nt][0]) + xv0.x;
        c[nt][1] = gelu_exact(c[nt][1]) + xv0.y;
        c[nt][2] = gelu_exact(c[nt][2]) + xv1.x;
        c[nt][3] = gelu_exact(c[nt][3]) + xv1.y;
        s0 += c[nt][0] + c[nt][1]; q0 += c[nt][0] * c[nt][0] + c[nt][1] * c[nt][1];
        s1 += c[nt][2] + c[nt][3]; q1 += c[nt][2] * c[nt][2] + c[nt][3] * c[nt][3];
    }
    #pragma unroll
    for (int o = 1; o <= 2; o <<= 1) {
        s0 += __shfl_xor_sync(FULLM, s0, o);
        q0 += __shfl_xor_sync(FULLM, q0, o);
        s1 += __shfl_xor_sync(FULLM, s1, o);
        q1 += __shfl_xor_sync(FULLM, q1, o);
    }
    float mu0 = s0 * (1.0f / 64.0f), var0 = q0 * (1.0f / 64.0f) - mu0 * mu0;
    float mu1 = s1 * (1.0f / 64.0f), var1 = q1 * (1.0f / 64.0f) - mu1 * mu1;
    float rs0 = rsqrtf(var0 + 1e-5f), rs1 = rsqrtf(var1 + 1e-5f);
    #pragma unroll
    for (int nt = 0; nt < 8; nt++) {
        int col = nt * 8 + 2 * tig;
        float2 gg = *reinterpret_cast<const float2*>(g1 + col);
        float2 bb = *reinterpret_cast<const float2*>(b1 + col);
        float2 o0 = make_float2((c[nt][0] - mu0) * rs0 * gg.x + bb.x,
                                (c[nt][1] - mu0) * rs0 * gg.y + bb.y);
        float2 o1 = make_float2((c[nt][2] - mu1) * rs1 * gg.x + bb.x,
                                (c[nt][3] - mu1) * rs1 * gg.y + bb.y);
        *reinterpret_cast<float2*>(g_h + r0 * D + col) = o0;
        *reinterpret_cast<float2*>(g_h + r1 * D + col) = o1;
    }
}

// ---------------- K7 fused: out = LN2(gelu(h@W1^T+b1)@W2^T + b2 + h) --------
#define SN7 136
__global__ void __launch_bounds__(256) k7_fused(
        float* __restrict__ out,
        const float* __restrict__ W1, const float* __restrict__ B1,
        const float* __restrict__ W2, const float* __restrict__ B2,
        const float* __restrict__ g2, const float* __restrict__ b2ln) {
    __shared__ unsigned sH[64 * SN6];        // 4608 >= 32*SN7 = 4352
    __shared__ unsigned sL[64 * SN6];
    int tid = threadIdx.x;
    for (int i = tid; i < 4096; i += 256) {
        int kp = i >> 7, j = i & 127;
        float2 wv = *reinterpret_cast<const float2*>(W1 + j * 64 + 2 * kp);
        unsigned h, l;
        split2(wv.x, wv.y, h, l);
        sH[kp * SN7 + j] = h;
        sL[kp * SN7 + j] = l;
    }
    __syncthreads();
    int wid = tid >> 5, lane = tid & 31;
    int gid = lane >> 2, tig = lane & 3;
    int strip = blockIdx.x * 8 + wid;
    if (strip >= NSTRIPS) strip = NSTRIPS - 1;
    int r0 = strip * 16 + gid, r1 = r0 + 8;

    float t[16][4];
    #pragma unroll
    for (int nt = 0; nt < 16; nt++)
        t[nt][0] = t[nt][1] = t[nt][2] = t[nt][3] = 0.f;

    #pragma unroll
    for (int kk = 0; kk < 4; kk++) {
        int kb = kk * 16, kp0 = kk * 8;
        float2 A0 = *reinterpret_cast<const float2*>(g_h + r0 * D + kb + 2 * tig);
        float2 A1 = *reinterpret_cast<const float2*>(g_h + r1 * D + kb + 2 * tig);
        float2 A2 = *reinterpret_cast<const float2*>(g_h + r0 * D + kb + 2 * tig + 8);
        float2 A3 = *reinterpret_cast<const float2*>(g_h + r1 * D + kb + 2 * tig + 8);
        unsigned ah0, al0, ah1, al1, ah2, al2, ah3, al3;
        split2(A0.x, A0.y, ah0, al0);
        split2(A1.x, A1.y, ah1, al1);
        split2(A2.x, A2.y, ah2, al2);
        split2(A3.x, A3.y, ah3, al3);
        const unsigned* rh0 = &sH[(kp0 + tig) * SN7];
        const unsigned* rh1 = &sH[(kp0 + tig + 4) * SN7];
        const unsigned* rl0 = &sL[(kp0 + tig) * SN7];
        const unsigned* rl1 = &sL[(kp0 + tig + 4) * SN7];
        #pragma unroll
        for (int nt = 0; nt < 16; nt++) {
            int bi = nt * 8 + gid;
            mma3b(t[nt], ah0, ah1, ah2, ah3, al0, al1, al2, al3,
                  rh0[bi], rh1[bi], rl0[bi], rl1[bi]);
        }
    }
    #pragma unroll
    for (int nt = 0; nt < 16; nt++) {
        int col = nt * 8 + 2 * tig;
        float2 bb = *reinterpret_cast<const float2*>(B1 + col);
        t[nt][0] = gelu_exact(t[nt][0] + bb.x);
        t[nt][1] = gelu_exact(t[nt][1] + bb.y);
        t[nt][2] = gelu_exact(t[nt][2] + bb.x);
        t[nt][3] = gelu_exact(t[nt][3] + bb.y);
    }

    __syncthreads();
    for (int i = tid; i < 4096; i += 256) {
        int kp = i >> 6, n = i & 63;
        float2 wv = *reinterpret_cast<const float2*>(W2 + n * 128 + 2 * kp);
        unsigned h, l;
        split2(wv.x, wv.y, h, l);
        sH[kp * SN6 + n] = h;
        sL[kp * SN6 + n] = l;
    }
    __syncthreads();

    float c[8][4];
    #pragma unroll
    for (int nt = 0; nt < 8; nt++)
        c[nt][0] = c[nt][1] = c[nt][2] = c[nt][3] = 0.f;

    #pragma unroll
    for (int kk = 0; kk < 8; kk++) {
        int kp0 = kk * 8;
        unsigned ah0, al0, ah1, al1, ah2, al2, ah3, al3;
        split2(t[2 * kk][0],     t[2 * kk][1],     ah0, al0);
        split2(t[2 * kk][2],     t[2 * kk][3],     ah1, al1);
        split2(t[2 * kk + 1][0], t[2 * kk + 1][1], ah2, al2);
        split2(t[2 * kk + 1][2], t[2 * kk + 1][3], ah3, al3);
        const unsigned* rh0 = &sH[(kp0 + tig) * SN6];
        const unsigned* rh1 = &sH[(kp0 + tig + 4) * SN6];
        const unsigned* rl0 = &sL[(kp0 + tig) * SN6];
        const unsigned* rl1 = &sL[(kp0 + tig + 4) * SN6];
        #pragma unroll
        for (int nt = 0; nt < 8; nt++) {
            int bi = nt * 8 + gid;
            mma3b(c[nt], ah0, ah1, ah2, ah3, al0, al1, al2, al3,
                  rh0[bi], rh1[bi], rl0[bi], rl1[bi]);
        }
    }

    float s0 = 0.f, q0 = 0.f, s1 = 0.f, q1 = 0.f;
    #pragma unroll
    for (int nt = 0; nt < 8; nt++) {
        int col = nt * 8 + 2 * tig;
        float2 bb = *reinterpret_cast<const float2*>(B2 + col);
        float2 h0 = *reinterpret_cast<const float2*>(g_h + r0 * D + col);
        float2 h1 = *reinterpret_cast<const float2*>(g_h + r1 * D + col);
        c[nt][0] += bb.x + h0.x;
        c[nt][1] += bb.y + h0.y;
        c[nt][2] += bb.x + h1.x;
        c[nt][3] += bb.y + h1.y;
        s0 += c[nt][0] + c[nt][1]; q0 += c[nt][0] * c[nt][0] + c[nt][1] * c[nt][1];
        s1 += c[nt][2] + c[nt][3]; q1 += c[nt][2] * c[nt][2] + c[nt][3] * c[nt][3];
    }
    #pragma unroll
    for (int o = 1; o <= 2; o <<= 1) {
        s0 += __shfl_xor_sync(FULLM, s0, o);
        q0 += __shfl_xor_sync(FULLM, q0, o);
        s1 += __shfl_xor_sync(FULLM, s1, o);
        q1 += __shfl_xor_sync(FULLM, q1, o);
    }
    float mu0 = s0 * (1.0f / 64.0f), var0 = q0 * (1.0f / 64.0f) - mu0 * mu0;
    float mu1 = s1 * (1.0f / 64.0f), var1 = q1 * (1.0f / 64.0f) - mu1 * mu1;
    float rs0 = rsqrtf(var0 + 1e-5f), rs1 = rsqrtf(var1 + 1e-5f);
    #pragma unroll
    for (int nt = 0; nt < 8; nt++) {
        int col = nt * 8 + 2 * tig;
        float2 gg = *reinterpret_cast<const float2*>(g2 + col);
        float2 bb = *reinterpret_cast<const float2*>(b2ln + col);
        float2 o0 = make_float2((c[nt][0] - mu0) * rs0 * gg.x + bb.x,
                                (c[nt][1] - mu0) * rs0 * gg.y + bb.y);
        float2 o1 = make_float2((c[nt][2] - mu1) * rs1 * gg.x + bb.x,
                                (c[nt][3] - mu1) * rs1 * gg.y + bb.y);
        *reinterpret_cast<float2*>(out + r0 * D + col) = o0;
        *reinterpret_cast<float2*>(out + r1 * D + col) = o1;
    }
}

// ---------------- launcher --------------------------------------------------
extern "C" void kernel_launch(void* const* d_in, const int* in_sizes, int n_in,
                              void* d_out, int out_size) {
    (void)in_sizes; (void)n_in; (void)out_size;
    const float* x    = (const float*)d_in[0];
    const int*   ei   = (const int*)  d_in[1];
    const float* rf   = (const float*)d_in[2];
    const float* Wp   = (const float*)d_in[3];
    const float* Wn   = (const float*)d_in[4];
    const float* attw = (const float*)d_in[5];
    const float* cf   = (const float*)d_in[6];
    const float* W1   = (const float*)d_in[7];
    const float* B1   = (const float*)d_in[8];
    const float* W2   = (const float*)d_in[9];
    const float* B2   = (const float*)d_in[10];
    const float* g1   = (const float*)d_in[11];
    const float* b1   = (const float*)d_in[12];
    const float* g2   = (const float*)d_in[13];
    const float* b2   = (const float*)d_in[14];
    float* out = (float*)d_out;

    const int GBLK = (NSTRIPS + 7) / 8;      // 782

    k12_prep<<<N_NODES / 8, 256>>>(x, attw, ei);
    k3a_scan<<<NTILE, 1024>>>();
    k3b_scan<<<1, 32>>>();
    k3c_apply<<<NTILE, 1024>>>();
    k4_scatter<<<N_EDGES / 256, 256>>>(ei, rf);
    k5_agg<<<N_NODES / 8, 256>>>(x, cf);
    k6_gemm_ln1<<<GBLK, 256>>>(x, Wp, Wn, g1, b1);
    k7_fused<<<GBLK, 256>>>(out, W1, B1, W2, B2, g2, b2);
}